// round 12
// baseline (speedup 1.0000x reference)
#include <cuda_runtime.h>
#include <math.h>

#define EPS      1e-6f
#define HIT_TOL  1e-3f
#define MIN_LEN  1.2e-6f

struct V3 { float x, y, z; };

__device__ __forceinline__ V3 v3(float x, float y, float z) { V3 r; r.x=x; r.y=y; r.z=z; return r; }
__device__ __forceinline__ V3 vsub(V3 a, V3 b) { return v3(a.x-b.x, a.y-b.y, a.z-b.z); }
__device__ __forceinline__ V3 vadd(V3 a, V3 b) { return v3(a.x+b.x, a.y+b.y, a.z+b.z); }
__device__ __forceinline__ V3 vscale(V3 a, float s) { return v3(a.x*s, a.y*s, a.z*s); }
__device__ __forceinline__ float vdot(V3 a, V3 b) { return a.x*b.x + a.y*b.y + a.z*b.z; }
__device__ __forceinline__ V3 vcross(V3 a, V3 b) {
    return v3(a.y*b.z - a.z*b.y,
              a.z*b.x - a.x*b.z,
              a.x*b.y - a.y*b.x);
}
__device__ __forceinline__ V3 shfl_v3(V3 v, int src) {
    v.x = __shfl_sync(0xFFFFFFFFu, v.x, src);
    v.y = __shfl_sync(0xFFFFFFFFu, v.y, src);
    v.z = __shfl_sync(0xFFFFFFFFu, v.z, src);
    return v;
}

__device__ __forceinline__ V3 load_vert(const float* __restrict__ mv, int i) {
    return v3(__ldg(mv + 3*i), __ldg(mv + 3*i + 1), __ldg(mv + 3*i + 2));
}

struct Tri { V3 v0, e1, e2; };

__device__ __forceinline__ Tri load_tri(const float* __restrict__ mesh_v,
                                        const int*   __restrict__ mesh_t,
                                        int f)
{
    int i0 = __ldg(mesh_t + 3*f);
    int i1 = __ldg(mesh_t + 3*f + 1);
    int i2 = __ldg(mesh_t + 3*f + 2);
    V3 p0 = load_vert(mesh_v, i0);
    V3 p1 = load_vert(mesh_v, i1);
    V3 p2 = load_vert(mesh_v, i2);
    Tri t;
    t.v0 = p0;
    t.e1 = vsub(p1, p0);
    t.e2 = vsub(p2, p0);
    return t;
}

// Moller-Trumbore (scalar), mirroring the reference's exact predicate structure.
// Used on the premask path (correctness-sensitive, unchanged from passing kernel).
__device__ __forceinline__ bool mt_hit(V3 ro, V3 rd, const Tri& T, float& t_out)
{
    V3 h = vcross(rd, T.e2);
    float a = vdot(T.e1, h);
    bool cond_a = fabsf(a) < EPS;
    float f = cond_a ? 0.0f : (1.0f / a);
    V3 s = vsub(ro, T.v0);
    float u = f * vdot(s, h);
    V3 q = vcross(s, T.e1);
    float v = f * vdot(rd, q);
    float t = f * vdot(T.e2, q);
    t_out = t;
    return (!cond_a) && (u >= 0.0f) && (u <= 1.0f) && (v >= 0.0f) && (u + v <= 1.0f) && (t > EPS);
}

// ============================ packed f32x2 math ============================
typedef unsigned long long u64;

__device__ __forceinline__ u64 pk2(float lo, float hi) {
    u64 r; asm("mov.b64 %0, {%1, %2};" : "=l"(r) : "f"(lo), "f"(hi)); return r;
}
__device__ __forceinline__ void upk2(u64 v, float& lo, float& hi) {
    asm("mov.b64 {%0, %1}, %2;" : "=f"(lo), "=f"(hi) : "l"(v));
}
__device__ __forceinline__ u64 mul2(u64 a, u64 b) {
    u64 r; asm("mul.rn.f32x2 %0, %1, %2;" : "=l"(r) : "l"(a), "l"(b)); return r;
}
__device__ __forceinline__ u64 fma2(u64 a, u64 b, u64 c) {
    u64 r; asm("fma.rn.f32x2 %0, %1, %2, %3;" : "=l"(r) : "l"(a), "l"(b), "l"(c)); return r;
}
// a - b  ==  fma(b, -1, a)   (1 packed op)
__device__ __forceinline__ u64 sub2(u64 a, u64 b) {
    const u64 NEG1 = 0xBF800000BF800000ULL;
    return fma2(b, NEG1, a);
}

struct V3P { u64 x, y, z; };

__device__ __forceinline__ V3P pk_pair(V3 a, V3 b) {        // (lane of A, lane of B)
    V3P r; r.x = pk2(a.x, b.x); r.y = pk2(a.y, b.y); r.z = pk2(a.z, b.z); return r;
}
__device__ __forceinline__ V3P pk_bcast(V3 a) {             // same in both halves
    V3P r; r.x = pk2(a.x, a.x); r.y = pk2(a.y, a.y); r.z = pk2(a.z, a.z); return r;
}
__device__ __forceinline__ V3P cross2(const V3P& a, const V3P& b) {
    V3P r;
    r.x = sub2(mul2(a.y, b.z), mul2(a.z, b.y));
    r.y = sub2(mul2(a.z, b.x), mul2(a.x, b.z));
    r.z = sub2(mul2(a.x, b.y), mul2(a.y, b.x));
    return r;
}
__device__ __forceinline__ u64 dot2(const V3P& a, const V3P& b) {
    return fma2(a.z, b.z, fma2(a.y, b.y, mul2(a.x, b.x)));
}
__device__ __forceinline__ V3P sub2v(const V3P& a, const V3P& b) {
    V3P r; r.x = sub2(a.x, b.x); r.y = sub2(a.y, b.y); r.z = sub2(a.z, b.z); return r;
}

// division-free predicate: hit with EPS < t < lim, all scaled by |a|
__device__ __forceinline__ bool mt_pred(float a, float su, float sv, float st, float lim)
{
    float abs_a = fabsf(a);
    if (abs_a < EPS) return false;
    float sgn = (a >= 0.0f) ? 1.0f : -1.0f;
    su *= sgn; sv *= sgn; st *= sgn;
    return (su >= 0.0f) && (su <= abs_a) &&
           (sv >= 0.0f) && (su + sv <= abs_a) &&
           (st > EPS * abs_a) && (st < lim * abs_a);
}

struct TriP { V3P v0, e1, e2; };

__device__ __forceinline__ TriP pk_tri(const Tri& A, const Tri& B) {
    TriP r; r.v0 = pk_pair(A.v0, B.v0); r.e1 = pk_pair(A.e1, B.e1); r.e2 = pk_pair(A.e2, B.e2);
    return r;
}

// test a PAIR of triangles against one segment (packed); per-tri results
__device__ __forceinline__ void mt_blocks2(const V3P& roP, const V3P& rdP,
                                           const TriP& T, float lim,
                                           bool& hitA, bool& hitB)
{
    V3P h  = cross2(rdP, T.e2);
    u64 a2 = dot2(T.e1, h);
    V3P s  = sub2v(roP, T.v0);
    u64 su = dot2(s, h);
    V3P q  = cross2(s, T.e1);
    u64 sv = dot2(rdP, q);
    u64 st = dot2(T.e2, q);
    float aA, aB, suA, suB, svA, svB, stA, stB;
    upk2(a2, aA, aB); upk2(su, suA, suB); upk2(sv, svA, svB); upk2(st, stA, stB);
    hitA = mt_pred(aA, suA, svA, stA, lim);
    hitB = mt_pred(aB, suB, svB, stB, lim);
}

// pair of triangles vs all 3 segments; per-tri "blocks" results
__device__ __forceinline__ void blocks_pair(const TriP& T,
                                            const V3P* roP, const V3P* rdP,
                                            float lim, bool& bA, bool& bB)
{
    bool hA, hB;
    bA = false; bB = false;
    #pragma unroll
    for (int i = 0; i < 3; i++) {
        mt_blocks2(roP[i], rdP[i], T, lim, hA, hB);
        bA |= hA; bB |= hB;
    }
}

// ---------------------------------------------------------------------------
// Single fused kernel (R6 structure): one thread per (t,r,p) path, fully
// warp-autonomous. Survivors tested warp-cooperatively with PACKED f32x2 MT
// (2 triangles per evaluation):
//   round 0  : triangles [0,64) prefetched into registers at kernel entry
//   round k>0: 128 triangles, 4 gathers per lane (MLP=4) = 2 packed pairs
// __any_sync early exit per round.
// ---------------------------------------------------------------------------
__global__ void __launch_bounds__(128)
fused_kernel(const float* __restrict__ mesh_v,
             const int*   __restrict__ mesh_t,
             const float* __restrict__ tx_v,
             const float* __restrict__ rx_v,
             const int*   __restrict__ pc,
             float*       __restrict__ out,
             int T, int R, int P, int NF)
{
    const int nPaths = T * R * P;
    int idx = blockIdx.x * blockDim.x + threadIdx.x;
    const bool valid = (idx < nPaths);
    if (idx >= nPaths) idx = nPaths - 1;       // clamp; keep warp converged
    const int lane = threadIdx.x & 31;

    // ---- prefetch occlusion chunk [0,64): 2 triangles per lane; issued first
    //      so the gather latency overlaps the dependent path-math chain ----
    const bool pf0_ok = (lane < NF);
    const bool pf1_ok = (lane + 32 < NF);
    Tri pfT0 = load_tri(mesh_v, mesh_t, pf0_ok ? lane : 0);
    Tri pfT1 = load_tri(mesh_v, mesh_t, pf1_ok ? lane + 32 : 0);

    // decode (t, r, p) -- row-major (T, R, P)
    const int t_idx = idx / (R * P);
    const int rem   = idx - t_idx * (R * P);
    const int r_idx = rem / P;
    const int p_idx = rem - r_idx * P;

    const int f0 = __ldg(pc + 2 * p_idx);
    const int f1 = __ldg(pc + 2 * p_idx + 1);

    Tri T0 = load_tri(mesh_v, mesh_t, f0);
    Tri T1 = load_tri(mesh_v, mesh_t, f1);

    // unit normals (match reference: fn / ||fn||)
    V3 fn0 = vcross(T0.e1, T0.e2);
    V3 n0  = vscale(fn0, 1.0f / sqrtf(vdot(fn0, fn0)));
    V3 fn1 = vcross(T1.e1, T1.e2);
    V3 n1  = vscale(fn1, 1.0f / sqrtf(vdot(fn1, fn1)));

    V3 txv = v3(__ldg(tx_v + 3*t_idx), __ldg(tx_v + 3*t_idx + 1), __ldg(tx_v + 3*t_idx + 2));
    V3 rxv = v3(__ldg(rx_v + 3*r_idx), __ldg(rx_v + 3*r_idx + 1), __ldg(rx_v + 3*r_idx + 2));

    V3 mv0 = T0.v0, mv1 = T1.v0;

    // forward scan: images
    V3 img0 = vsub(txv, vscale(n0, 2.0f * vdot(vsub(txv, mv0), n0)));
    V3 img1 = vsub(img0, vscale(n1, 2.0f * vdot(vsub(img0, mv1), n1)));

    // backward scan: reflection points
    V3 u1 = vsub(rxv, img1);
    float un1 = vdot(u1, n1);
    float vn1 = vdot(vsub(img1, mv1), n1);
    float tt1 = (un1 == 0.0f) ? 0.0f : (-vn1 / un1);
    V3 p1v = vadd(img1, vscale(u1, tt1));

    V3 u0 = vsub(p1v, img0);
    float un0 = vdot(u0, n0);
    float vn0 = vdot(vsub(img0, mv0), n0);
    float tt0 = (un0 == 0.0f) ? 0.0f : (-vn0 / un0);
    V3 p0v = vadd(img0, vscale(u0, tt0));

    // segments
    V3 rd0 = vsub(p0v, txv);
    V3 rd1 = vsub(p1v, p0v);
    V3 rd2 = vsub(rxv, p1v);

    bool too_small = (vdot(rd0, rd0) < MIN_LEN) ||
                     (vdot(rd1, rd1) < MIN_LEN) ||
                     (vdot(rd2, rd2) < MIN_LEN);

    float tdum;
    bool inside = mt_hit(txv, rd0, T0, tdum) && mt_hit(p0v, rd1, T1, tdum);

    float dp0 = vdot(vsub(txv, mv0), n0);
    float dn0 = vdot(vsub(p1v, mv0), n0);
    float dp1 = vdot(vsub(p0v, mv1), n1);
    float dn1 = vdot(vsub(rxv, mv1), n1);
    bool valid_refl = (dp0 * dn0 >= 0.0f) && (dp1 * dn1 >= 0.0f);

    bool premask = inside && valid_refl && !too_small && valid;

    // write the unconditional outputs NOW so stores overlap occlusion
    if (valid) {
        float* fp = out + (size_t)idx * 12;
        ((float4*)fp)[0] = make_float4(txv.x, txv.y, txv.z, p0v.x);
        ((float4*)fp)[1] = make_float4(p0v.y, p0v.z, p1v.x, p1v.y);
        ((float4*)fp)[2] = make_float4(p1v.z, rxv.x, rxv.y, rxv.z);

        float* ob = out + (size_t)nPaths * 12 + (size_t)idx * 4;
        ((float4*)ob)[0] = make_float4((float)t_idx, (float)f0, (float)f1, (float)r_idx);
    }

    // ---- warp-cooperative occlusion for survivors (packed f32x2) ----
    bool blocked = false;
    unsigned ball = __ballot_sync(0xFFFFFFFFu, premask);
    const float lim = 1.0f - HIT_TOL;
    while (ball) {
        const int src = __ffs(ball) - 1;
        ball &= ball - 1;
        V3 a0 = shfl_v3(txv, src);
        V3 a1 = shfl_v3(p0v, src);
        V3 a2 = shfl_v3(p1v, src);
        V3 a3 = shfl_v3(rxv, src);
        V3 d0 = vsub(a1, a0);
        V3 d1 = vsub(a2, a1);
        V3 d2 = vsub(a3, a2);

        // pack segment vectors ONCE per survivor (broadcast halves)
        V3P roP[3] = { pk_bcast(a0), pk_bcast(a1), pk_bcast(a2) };
        V3P rdP[3] = { pk_bcast(d0), pk_bcast(d1), pk_bcast(d2) };

        // round 0: 64 prefetched triangles = 1 packed pair, flops + ballot
        bool bA, bB;
        {
            TriP Tp = pk_tri(pfT0, pfT1);
            blocks_pair(Tp, roP, rdP, lim, bA, bB);
        }
        bool b0 = (pf0_ok && bA) || (pf1_ok && bB);
        bool blk = __any_sync(0xFFFFFFFFu, b0);

        // remaining rounds: 128 triangles = 4 gathers (MLP=4) = 2 packed pairs
        if (!blk) {
            for (int base = 64; base < NF && !blk; base += 128) {
                int fA = base + lane;
                int fB = fA + 32;
                int fC = fA + 64;
                int fD = fA + 96;
                bool okA = fA < NF, okB = fB < NF, okC = fC < NF, okD = fD < NF;
                Tri TA = load_tri(mesh_v, mesh_t, okA ? fA : 0);
                Tri TB = load_tri(mesh_v, mesh_t, okB ? fB : 0);
                Tri TC = load_tri(mesh_v, mesh_t, okC ? fC : 0);
                Tri TD = load_tri(mesh_v, mesh_t, okD ? fD : 0);

                bool bC, bD;
                TriP Tab = pk_tri(TA, TB);
                blocks_pair(Tab, roP, rdP, lim, bA, bB);
                TriP Tcd = pk_tri(TC, TD);
                blocks_pair(Tcd, roP, rdP, lim, bC, bD);

                bool b = (okA && bA) || (okB && bB) || (okC && bC) || (okD && bD);
                blk = __any_sync(0xFFFFFFFFu, b);
            }
        }
        if (lane == src) blocked = blk;
    }

    bool mask = premask && !blocked;

    if (valid)
        out[(size_t)nPaths * 16 + idx] = mask ? 1.0f : 0.0f;
}

// ---------------------------------------------------------------------------
extern "C" void kernel_launch(void* const* d_in, const int* in_sizes, int n_in,
                              void* d_out, int out_size)
{
    const float* mesh_v = (const float*)d_in[0];   // (NV, 3) f32
    const int*   mesh_t = (const int*)  d_in[1];   // (NF, 3) i32
    const float* tx_v   = (const float*)d_in[2];   // (T, 3)  f32
    const float* rx_v   = (const float*)d_in[3];   // (R, 3)  f32
    const int*   pc     = (const int*)  d_in[4];   // (P, 2)  i32

    const int NF = in_sizes[1] / 3;
    const int T  = in_sizes[2] / 3;
    const int R  = in_sizes[3] / 3;
    const int P  = in_sizes[4] / 2;   // ORDER = 2

    const int nPaths = T * R * P;
    const int threads = 128;
    const int blocks = (nPaths + threads - 1) / threads;
    fused_kernel<<<blocks, threads>>>(mesh_v, mesh_t, tx_v, rx_v, pc,
                                      (float*)d_out, T, R, P, NF);
}